// round 8
// baseline (speedup 1.0000x reference)
#include <cuda_runtime.h>
#include <cuda_bf16.h>

typedef __nv_bfloat16 bf16;

#define NT 512
constexpr float LRATE = 0.01f;
constexpr float DYSCALE = 2.0f / 2097152.0f;   // 2 / (B * 128*128)

// ---- smem tensor arena offsets (floats) ----
constexpr int T_P0=0,     T_P1=16384, T_P2=20480, T_P3=21504, T_P4=21760,
              T_F=21824,  T_Z=21888,  T_DD=21920, T_Q0=21984, T_Q1=22240,
              T_Q2=23264, T_Q3=27360, T_END=43744;
constexpr int NPARAM_PAD = 5752;
constexpr int WE_FLOATS = 5*260 + 4;                       // 5 layers x (4c x 65)
constexpr int SMEM_FLOATS = T_END + NPARAM_PAD + 320 + WE_FLOATS;
constexpr int SMEM_BYTES  = SMEM_FLOATS * 4;               // ~204.5 KB

// ---- bf16 arena offsets (halfs): gradient-path tensors ----
constexpr int HU0=0,      HU1=65536,  HU2=81920,  HU3=86016,  HU4=87040,  HU5=87296,
              HV0=87360,  HV1=87616,  HV2=88640,  HV3=92736,  HV4=109120,
              HZU=174656, HDU=174688, HDY=174752, HGA=191136, HGB=256672;
constexpr int SSCH = 273056;

constexpr int IX0=0, IX1=16384, IX2=20480, IX3=21504, IX4=21760, SIDX=21824;

__device__ float          g_q4[128ull * 65536];
__device__ bf16           g_scratchh[128ull * SSCH];
__device__ unsigned char  g_idxbuf[128 * SIDX];

// ---- smem param layout (floats) ----
constexpr int PW0=0, PEB=36, PEW=60, PLEW=780, PLEB=2828, PLDW=2860, PLDB=4908,
              PDW=4972, PDB=5692, PWO=5712, PBO=5748;

__device__ __forceinline__ float tanhap(float x){ float y; asm("tanh.approx.f32 %0, %1;" : "=f"(y) : "f"(x)); return y; }
__device__ __forceinline__ float sigm(float u){ return fmaf(tanhap(0.5f*u), 0.5f, 0.5f); }
__device__ __forceinline__ float swish_f(float u){ return u * sigm(u); }
__device__ __forceinline__ float swish_d(float u){ float s = sigm(u); return s * fmaf(u, 1.0f - s, 1.0f); }

__device__ __forceinline__ float bf2f(bf16 v){ return __bfloat162float(v); }
__device__ __forceinline__ bf16  f2bf(float v){ return __float2bfloat16(v); }
__device__ __forceinline__ float4 ld4h(const bf16* p){
    __nv_bfloat162 a = reinterpret_cast<const __nv_bfloat162*>(p)[0];
    __nv_bfloat162 b = reinterpret_cast<const __nv_bfloat162*>(p)[1];
    return make_float4(__bfloat162float(a.x), __bfloat162float(a.y),
                       __bfloat162float(b.x), __bfloat162float(b.y));
}
__device__ __forceinline__ float4 ldz4h(const bf16* p, bool v){
    return v ? ld4h(p) : make_float4(0.f,0.f,0.f,0.f);
}
__device__ __forceinline__ void st4h(bf16* p, float4 v){
    reinterpret_cast<__nv_bfloat162*>(p)[0] = __floats2bfloat162_rn(v.x, v.y);
    reinterpret_cast<__nv_bfloat162*>(p)[1] = __floats2bfloat162_rn(v.z, v.w);
}
__device__ __forceinline__ float4 ldz4(const float* p, bool v){
    return v ? *reinterpret_cast<const float4*>(p) : make_float4(0.f,0.f,0.f,0.f);
}
__device__ __forceinline__ float dot4a(float a, const float* w, float4 p){
    return fmaf(w[0],p.x, fmaf(w[1],p.y, fmaf(w[2],p.z, fmaf(w[3],p.w, a))));
}
__device__ __forceinline__ void axpy4(float4& a, float s, const float* w){
    a.x = fmaf(s,w[0],a.x); a.y = fmaf(s,w[1],a.y); a.z = fmaf(s,w[2],a.z); a.w = fmaf(s,w[3],a.w);
}
__device__ __forceinline__ void accum4(float* accK, float g, float4 p){
    accK[0]  = fmaf(g,p.x,accK[0]);  accK[9]  = fmaf(g,p.y,accK[9]);
    accK[18] = fmaf(g,p.z,accK[18]); accK[27] = fmaf(g,p.w,accK[27]);
}
__device__ __forceinline__ int nh(int i){ return ((i & 15) << 2) + (i >> 4); }

__device__ __forceinline__ void pool1(float v0,float v1,float v2,float v3,
                                      float& m, unsigned char& id){
    v0 = swish_f(v0); v1 = swish_f(v1); v2 = swish_f(v2); v3 = swish_f(v3);
    m = v0; id = 0;
    if (v1 > m) { m = v1; id = 1; }
    if (v2 > m) { m = v2; id = 2; }
    if (v3 > m) { m = v3; id = 3; }
}

// ============================================================================
// conv0pool: 1->4 conv (planar in) fused with swish+2x2 maxpool.
// ============================================================================
template<int R,bool FIRST>
__device__ __noinline__ void conv0pool(const float* __restrict__ in, const float* w,
                                       const float* b, bf16* __restrict__ uh,
                                       float* pOut, unsigned char* __restrict__ idx)
{
    constexpr int NX = R/4, Ro = R/2;
    float wr[36];
    #pragma unroll
    for (int k = 0; k < 9; ++k)
        #pragma unroll
        for (int o = 0; o < 4; ++o) wr[k*4+o] = w[o*9+k];
    const float4 bb = make_float4(b[0],b[1],b[2],b[3]);
    for (int t = threadIdx.x; t < (R/2)*NX; t += NT) {
        int xv = t % NX, yp = t / NX, x0 = xv*4, y0 = 2*yp;
        float4 a0[4] = {bb,bb,bb,bb};
        float4 a1[4] = {bb,bb,bb,bb};
        #pragma unroll
        for (int iy = 0; iy < 4; ++iy) {
            int yy = y0 - 1 + iy; if ((unsigned)yy >= (unsigned)R) continue;
            const float* row = in + yy*R;
            float4 v = *reinterpret_cast<const float4*>(row + x0);
            float s[6];
            s[0] = (x0 > 0)   ? row[x0-1] : 0.f;
            s[1]=v.x; s[2]=v.y; s[3]=v.z; s[4]=v.w;
            s[5] = (x0+4 < R) ? row[x0+4] : 0.f;
            if (iy <= 2) {
                #pragma unroll
                for (int j = 0; j < 4; ++j)
                    #pragma unroll
                    for (int kx = 0; kx < 3; ++kx)
                        axpy4(a0[j], s[j+kx], &wr[(iy*3+kx)*4]);
            }
            if (iy >= 1) {
                #pragma unroll
                for (int j = 0; j < 4; ++j)
                    #pragma unroll
                    for (int kx = 0; kx < 3; ++kx)
                        axpy4(a1[j], s[j+kx], &wr[((iy-1)*3+kx)*4]);
            }
        }
        if (FIRST) {
            int ub0 = (y0*R + x0)*4, ub1 = ub0 + R*4;
            #pragma unroll
            for (int j = 0; j < 4; ++j) { st4h(uh + ub0 + j*4, a0[j]); st4h(uh + ub1 + j*4, a1[j]); }
        }
        int xo = x0 >> 1;
        #pragma unroll
        for (int jj = 0; jj < 2; ++jj) {
            int j = 2*jj;
            float4 q00 = a0[j], q01 = a0[j+1], q10 = a1[j], q11 = a1[j+1];
            float pm[4]; unsigned char im[4];
            pool1(q00.x, q01.x, q10.x, q11.x, pm[0], im[0]);
            pool1(q00.y, q01.y, q10.y, q11.y, pm[1], im[1]);
            pool1(q00.z, q01.z, q10.z, q11.z, pm[2], im[2]);
            pool1(q00.w, q01.w, q10.w, q11.w, pm[3], im[3]);
            int ob = (yp*Ro + xo + jj)*4;
            *reinterpret_cast<float4*>(pOut + ob) = make_float4(pm[0],pm[1],pm[2],pm[3]);
            if (FIRST) *reinterpret_cast<uchar4*>(idx + ob) = make_uchar4(im[0],im[1],im[2],im[3]);
        }
    }
}

// ============================================================================
// conv4pool: 4->4 conv NHWC fused with swish+2x2 maxpool; thread owns o.
// ============================================================================
template<int R,bool FIRST>
__device__ __noinline__ void conv4pool(const float* in, const float* w,
                                       const float* b, bf16* __restrict__ uh,
                                       float* pOut, unsigned char* __restrict__ idx)
{
    constexpr int NX = R/4, Ro = R/2;
    const int o = threadIdx.x & 3;
    float wr[36];
    #pragma unroll
    for (int k = 0; k < 9; ++k)
        #pragma unroll
        for (int c = 0; c < 4; ++c) wr[k*4+c] = w[(o*4+c)*9+k];
    const float bb = b[o];
    for (int t = threadIdx.x; t < 4*(R/2)*NX; t += NT) {
        int r2 = t >> 2;
        int xv = r2 % NX, yp = r2 / NX, x0 = xv*4, y0 = 2*yp;
        float a0[4] = {bb,bb,bb,bb};
        float a1[4] = {bb,bb,bb,bb};
        #pragma unroll
        for (int iy = 0; iy < 4; ++iy) {
            int yy = y0 - 1 + iy; if ((unsigned)yy >= (unsigned)R) continue;
            const float* row = in + yy*R*4;
            float4 p[6];
            #pragma unroll
            for (int k = 0; k < 6; ++k) {
                int xx = x0 - 1 + k;
                p[k] = ldz4(row + xx*4, (unsigned)xx < (unsigned)R);
            }
            if (iy <= 2) {
                #pragma unroll
                for (int j = 0; j < 4; ++j)
                    #pragma unroll
                    for (int kx = 0; kx < 3; ++kx)
                        a0[j] = dot4a(a0[j], &wr[(iy*3+kx)*4], p[j+kx]);
            }
            if (iy >= 1) {
                #pragma unroll
                for (int j = 0; j < 4; ++j)
                    #pragma unroll
                    for (int kx = 0; kx < 3; ++kx)
                        a1[j] = dot4a(a1[j], &wr[((iy-1)*3+kx)*4], p[j+kx]);
            }
        }
        if (FIRST) {
            int ub0 = (y0*R + x0)*4 + o, ub1 = ub0 + R*4;
            #pragma unroll
            for (int j = 0; j < 4; ++j) { uh[ub0 + j*4] = f2bf(a0[j]); uh[ub1 + j*4] = f2bf(a1[j]); }
        }
        int xo = x0 >> 1;
        #pragma unroll
        for (int jj = 0; jj < 2; ++jj) {
            int j = 2*jj;
            float m; unsigned char id;
            pool1(a0[j], a0[j+1], a1[j], a1[j+1], m, id);
            int ob = (yp*Ro + xo + jj)*4 + o;
            pOut[ob] = m;
            if (FIRST) idx[ob] = id;
        }
    }
}

// ============================================================================
// conv4b: 4->4 NHWC (last encoder conv): pre bf16 (FIRST), act fp32
// ============================================================================
template<int R,bool FIRST>
__device__ __noinline__ void conv4b(const float* in, const float* w,
                                    const float* b, bf16* __restrict__ outPre,
                                    float* outAct)
{
    constexpr int NX = R/4;
    const int o = threadIdx.x & 3;
    float wr[36];
    #pragma unroll
    for (int k = 0; k < 9; ++k)
        #pragma unroll
        for (int c = 0; c < 4; ++c) wr[k*4+c] = w[(o*4+c)*9+k];
    const float bb = b[o];
    for (int t = threadIdx.x; t < 4*(R/2)*NX; t += NT) {
        int r2 = t >> 2;
        int xv = r2 % NX, yp = r2 / NX, x0 = xv*4, y0 = 2*yp;
        float a0[4] = {bb,bb,bb,bb};
        float a1[4] = {bb,bb,bb,bb};
        #pragma unroll
        for (int iy = 0; iy < 4; ++iy) {
            int yy = y0 - 1 + iy; if ((unsigned)yy >= (unsigned)R) continue;
            const float* row = in + yy*R*4;
            float4 p[6];
            #pragma unroll
            for (int k = 0; k < 6; ++k) {
                int xx = x0 - 1 + k;
                p[k] = ldz4(row + xx*4, (unsigned)xx < (unsigned)R);
            }
            if (iy <= 2) {
                #pragma unroll
                for (int j = 0; j < 4; ++j)
                    #pragma unroll
                    for (int kx = 0; kx < 3; ++kx)
                        a0[j] = dot4a(a0[j], &wr[(iy*3+kx)*4], p[j+kx]);
            }
            if (iy >= 1) {
                #pragma unroll
                for (int j = 0; j < 4; ++j)
                    #pragma unroll
                    for (int kx = 0; kx < 3; ++kx)
                        a1[j] = dot4a(a1[j], &wr[((iy-1)*3+kx)*4], p[j+kx]);
            }
        }
        int base0 = (y0*R + x0)*4 + o, base1 = base0 + R*4;
        #pragma unroll
        for (int j = 0; j < 4; ++j) {
            if (FIRST) { outPre[base0 + j*4] = f2bf(a0[j]); outPre[base1 + j*4] = f2bf(a1[j]); }
            outAct[base0 + j*4] = swish_f(a0[j]);
            outAct[base1 + j*4] = swish_f(a1[j]);
        }
    }
}

// ============================================================================
// convup: 4->4 NHWC, fused 2x nearest upsample; act fp32 always, pre bf16 if ST
// ============================================================================
template<int R,bool ST>
__device__ __noinline__ void convup(const float* in, const float* w,
                                    const float* b, bf16* __restrict__ outPre,
                                    float* outAct)
{
    constexpr int NX = R/4, H = R/2;
    const int o = threadIdx.x & 3;
    const int parity = (threadIdx.x >> 2) & 1;
    float FU[32];
    #pragma unroll
    for (int c = 0; c < 4; ++c) {
        const float* wb = w + (o*4 + c)*9;
        float A0,A1,A2,B0,B1,B2;
        if (!parity) { A0=wb[0];A1=wb[1];A2=wb[2]; B0=wb[3]+wb[6];B1=wb[4]+wb[7];B2=wb[5]+wb[8]; }
        else         { A0=wb[0]+wb[3];A1=wb[1]+wb[4];A2=wb[2]+wb[5]; B0=wb[6];B1=wb[7];B2=wb[8]; }
        FU[0*4+c]=A0;  FU[1*4+c]=A2;  FU[2*4+c]=A0+A1; FU[3*4+c]=A1+A2;
        FU[16+0*4+c]=B0; FU[16+1*4+c]=B2; FU[16+2*4+c]=B0+B1; FU[16+3*4+c]=B1+B2;
    }
    const float bb = b[o];
    constexpr int ITEMS = 8*(H/2)*NX;
    for (int t = threadIdx.x; t < ITEMS; t += NT) {
        int q = t >> 3;
        int xv = q % NX, yhp = q / NX;
        int yh0 = 2*yhp, x0 = xv*4, hx = x0>>1;
        float a0[4] = {bb,bb,bb,bb};
        float a1[4] = {bb,bb,bb,bb};
        #pragma unroll
        for (int rr = 0; rr < 3; ++rr) {
            int srow_i = yh0 - 1 + parity + rr;
            if ((unsigned)srow_i >= (unsigned)H) continue;
            const float* srow = in + srow_i*H*4;
            float4 s0 = ldz4(srow + (hx-1)*4, hx > 0);
            float4 s1 = *reinterpret_cast<const float4*>(srow + hx*4);
            float4 s2 = *reinterpret_cast<const float4*>(srow + (hx+1)*4);
            float4 s3 = ldz4(srow + (hx+2)*4, hx+2 < H);
            if (rr <= 1) {
                const float* F = FU + rr*16;
                a0[0] = dot4a(dot4a(a0[0], F+0*4, s0), F+3*4, s1);
                a0[1] = dot4a(dot4a(a0[1], F+2*4, s1), F+1*4, s2);
                a0[2] = dot4a(dot4a(a0[2], F+0*4, s1), F+3*4, s2);
                a0[3] = dot4a(dot4a(a0[3], F+2*4, s2), F+1*4, s3);
            }
            if (rr >= 1) {
                const float* F = FU + (rr-1)*16;
                a1[0] = dot4a(dot4a(a1[0], F+0*4, s0), F+3*4, s1);
                a1[1] = dot4a(dot4a(a1[1], F+2*4, s1), F+1*4, s2);
                a1[2] = dot4a(dot4a(a1[2], F+0*4, s1), F+3*4, s2);
                a1[3] = dot4a(dot4a(a1[3], F+2*4, s2), F+1*4, s3);
            }
        }
        int y0 = 2*yh0 + parity;
        int base0 = (y0*R + x0)*4 + o, base1 = base0 + 2*R*4;
        #pragma unroll
        for (int j = 0; j < 4; ++j) {
            if (ST) { outPre[base0 + j*4] = f2bf(a0[j]); outPre[base1 + j*4] = f2bf(a1[j]); }
            outAct[base0 + j*4] = swish_f(a0[j]);
            outAct[base1 + j*4] = swish_f(a1[j]);
        }
    }
}

// ============================================================================
// convfin: 4->1, NHWC in. MODE 0: y -> fp32 planar. MODE 2: dy -> bf16 planar.
// ============================================================================
template<int R,int MODE>
__device__ __noinline__ void convfin(const float* in, const float* w,
                                     float b0, void* __restrict__ outp,
                                     const float* __restrict__ xref)
{
    constexpr int NX = R/4;
    float wr[36];
    #pragma unroll
    for (int k = 0; k < 9; ++k)
        #pragma unroll
        for (int c = 0; c < 4; ++c) wr[k*4+c] = w[c*9+k];
    for (int t = threadIdx.x; t < (R/2)*NX; t += NT) {
        int xv = t % NX, yp = t / NX, x0 = xv*4, y0 = 2*yp;
        float a0[4] = {b0,b0,b0,b0};
        float a1[4] = {b0,b0,b0,b0};
        #pragma unroll
        for (int iy = 0; iy < 4; ++iy) {
            int yy = y0 - 1 + iy; if ((unsigned)yy >= (unsigned)R) continue;
            const float* row = in + yy*R*4;
            float4 p[6];
            #pragma unroll
            for (int k = 0; k < 6; ++k) {
                int xx = x0 - 1 + k;
                p[k] = ldz4(row + xx*4, (unsigned)xx < (unsigned)R);
            }
            if (iy <= 2) {
                #pragma unroll
                for (int j = 0; j < 4; ++j)
                    #pragma unroll
                    for (int kx = 0; kx < 3; ++kx)
                        a0[j] = dot4a(a0[j], &wr[(iy*3+kx)*4], p[j+kx]);
            }
            if (iy >= 1) {
                #pragma unroll
                for (int j = 0; j < 4; ++j)
                    #pragma unroll
                    for (int kx = 0; kx < 3; ++kx)
                        a1[j] = dot4a(a1[j], &wr[((iy-1)*3+kx)*4], p[j+kx]);
            }
        }
        #pragma unroll
        for (int rr = 0; rr < 2; ++rr) {
            float* a = rr ? a1 : a0;
            int y = y0 + rr;
            if constexpr (MODE == 2) {
                float4 xr = *reinterpret_cast<const float4*>(xref + y*R + x0);
                float4 ov = make_float4((a[0]-xr.x)*DYSCALE,(a[1]-xr.y)*DYSCALE,
                                        (a[2]-xr.z)*DYSCALE,(a[3]-xr.w)*DYSCALE);
                st4h(reinterpret_cast<bf16*>(outp) + y*R + x0, ov);
            } else {
                *reinterpret_cast<float4*>(reinterpret_cast<float*>(outp) + y*R + x0) =
                    make_float4(a[0],a[1],a[2],a[3]);
            }
        }
    }
}

// ============================================================================
// dgrad of final conv (tid/nth parametrized for warp-split phases)
// ============================================================================
template<int R>
__device__ __noinline__ void dgrad_fin(const bf16* __restrict__ dout, const float* w,
                                       const bf16* __restrict__ upre, bf16* __restrict__ din,
                                       int tid, int nth)
{
    constexpr int NX = R/4;
    float wf[36];
    #pragma unroll
    for (int k = 0; k < 9; ++k)
        #pragma unroll
        for (int c = 0; c < 4; ++c) wf[k*4+c] = w[c*9 + 8-k];
    for (int t = tid; t < (R/2)*NX; t += nth) {
        int xv = t % NX, yp = t / NX, x0 = xv*4, y0 = 2*yp;
        float4 a0[4] = {};
        float4 a1[4] = {};
        #pragma unroll
        for (int iy = 0; iy < 4; ++iy) {
            int yy = y0 - 1 + iy; if ((unsigned)yy >= (unsigned)R) continue;
            const bf16* row = dout + yy*R;
            float4 v = ld4h(row + x0);
            float s[6];
            s[0] = (x0 > 0)   ? bf2f(row[x0-1]) : 0.f;
            s[1]=v.x; s[2]=v.y; s[3]=v.z; s[4]=v.w;
            s[5] = (x0+4 < R) ? bf2f(row[x0+4]) : 0.f;
            if (iy <= 2) {
                #pragma unroll
                for (int j = 0; j < 4; ++j)
                    #pragma unroll
                    for (int kx = 0; kx < 3; ++kx)
                        axpy4(a0[j], s[j+kx], &wf[(iy*3+kx)*4]);
            }
            if (iy >= 1) {
                #pragma unroll
                for (int j = 0; j < 4; ++j)
                    #pragma unroll
                    for (int kx = 0; kx < 3; ++kx)
                        axpy4(a1[j], s[j+kx], &wf[((iy-1)*3+kx)*4]);
            }
        }
        #pragma unroll
        for (int rr = 0; rr < 2; ++rr) {
            float4* a = rr ? a1 : a0;
            int base = ((y0+rr)*R + x0)*4;
            #pragma unroll
            for (int j = 0; j < 4; ++j) {
                float4 u4 = ld4h(upre + base + j*4);
                a[j].x *= swish_d(u4.x); a[j].y *= swish_d(u4.y);
                a[j].z *= swish_d(u4.z); a[j].w *= swish_d(u4.w);
                st4h(din + base + j*4, a[j]);
            }
        }
    }
}

// ============================================================================
// dgrad4pb: 4->4 encoder dgrad at R with FUSED maxpool-backward scatter:
// writes du at 2R (zero-filled except argmax positions, * swish'(u)).
// ============================================================================
template<int R>
__device__ __noinline__ void dgrad4pb(const bf16* __restrict__ dout, const float* w,
                                      const unsigned char* __restrict__ idx,
                                      const bf16* __restrict__ u, bf16* __restrict__ du,
                                      int tid, int nth)
{
    constexpr int NX = R/4, R2 = 2*R;
    const int c = tid & 3;
    const bf16 Z = f2bf(0.f);
    float wf[36];
    #pragma unroll
    for (int k = 0; k < 9; ++k)
        #pragma unroll
        for (int o = 0; o < 4; ++o) wf[k*4+o] = w[(o*4+c)*9 + 8-k];
    for (int t = tid; t < 4*(R/2)*NX; t += nth) {
        int r2 = t >> 2;
        int xv = r2 % NX, yp = r2 / NX, x0 = xv*4, y0 = 2*yp;
        float a0[4] = {};
        float a1[4] = {};
        #pragma unroll
        for (int iy = 0; iy < 4; ++iy) {
            int yy = y0 - 1 + iy; if ((unsigned)yy >= (unsigned)R) continue;
            const bf16* row = dout + yy*R*4;
            float4 p[6];
            #pragma unroll
            for (int k = 0; k < 6; ++k) {
                int xx = x0 - 1 + k;
                p[k] = ldz4h(row + xx*4, (unsigned)xx < (unsigned)R);
            }
            if (iy <= 2) {
                #pragma unroll
                for (int j = 0; j < 4; ++j)
                    #pragma unroll
                    for (int kx = 0; kx < 3; ++kx)
                        a0[j] = dot4a(a0[j], &wf[(iy*3+kx)*4], p[j+kx]);
            }
            if (iy >= 1) {
                #pragma unroll
                for (int j = 0; j < 4; ++j)
                    #pragma unroll
                    for (int kx = 0; kx < 3; ++kx)
                        a1[j] = dot4a(a1[j], &wf[((iy-1)*3+kx)*4], p[j+kx]);
            }
        }
        #pragma unroll
        for (int rr = 0; rr < 2; ++rr) {
            const float* a = rr ? a1 : a0;
            int y = y0 + rr;
            #pragma unroll
            for (int j = 0; j < 4; ++j) {
                int x = x0 + j;
                int cell = (y*R + x)*4 + c;
                int id = idx[cell];
                int sy = id >> 1, sx = id & 1;
                int pb = ((2*y)*R2 + 2*x)*4 + c;
                int psel = pb + (sy*R2 + sx)*4;
                bf16 ov = f2bf(a[j] * swish_d(bf2f(u[psel])));
                du[pb]          = (id == 0) ? ov : Z;
                du[pb+4]        = (id == 1) ? ov : Z;
                du[pb+R2*4]     = (id == 2) ? ov : Z;
                du[pb+R2*4+4]   = (id == 3) ? ov : Z;
            }
        }
    }
}

// ============================================================================
// dupv: backward of (up->conv); wE table read from smem (per-layer, per-c)
// ============================================================================
template<int R>
__device__ __noinline__ void dupv(const bf16* __restrict__ dout, const float* sWE, int layer,
                                  const bf16* __restrict__ upre, bf16* __restrict__ din,
                                  int tid, int nth)
{
    constexpr int H = R/2, NXH = H/4;
    const int c = tid & 3;
    const float* wE = sWE + layer*260 + c*65;
    for (int t = tid; t < 4*H*NXH; t += nth) {
        int r2 = t >> 2;
        int vv = r2 % NXH, u = r2 / NXH, v0 = vv*4;
        int r0 = 2*u - 1;
        float a[4] = {};
        #pragma unroll
        for (int i = 0; i < 4; ++i) {
            int rr = r0 + i; if ((unsigned)rr >= (unsigned)R) continue;
            const bf16* row = dout + rr*R*4;
            float4 q[10];
            #pragma unroll
            for (int m = 0; m < 10; ++m) {
                int px = 2*v0 - 1 + m;
                q[m] = ldz4h(row + px*4, (unsigned)px < (unsigned)R);
            }
            #pragma unroll
            for (int j = 0; j < 4; ++j)
                #pragma unroll
                for (int kk = 0; kk < 4; ++kk)
                    a[j] = dot4a(a[j], &wE[(i*4+kk)*4], q[2*j+kk]);
        }
        int base = (u*H + v0)*4 + c;
        #pragma unroll
        for (int j = 0; j < 4; ++j) {
            float up = bf2f(upre[base + j*4]);
            din[base + j*4] = f2bf(a[j] * swish_d(up));
        }
    }
}

// ============================================================================
// wgrad accumulators — NO internal barriers; sRed pre-zeroed; update deferred
// ============================================================================
template<int R,bool UP>
__device__ __noinline__ void wgrad4_acc(const bf16* __restrict__ dout, const float* in,
                                        float* sRed, int tid, int nth)
{
    constexpr int NX = R/4, H = R/2;
    const int o = tid & 3;
    float acc[36]; float accb = 0.f;
    #pragma unroll
    for (int i = 0; i < 36; ++i) acc[i] = 0.f;

    for (int pv = tid >> 2; pv < R*NX; pv += nth >> 2) {
        int y = pv / NX, x0 = (pv % NX)*4;
        const bf16* db = dout + (y*R + x0)*4 + o;
        float g0 = bf2f(db[0]), g1 = bf2f(db[4]), g2 = bf2f(db[8]), g3 = bf2f(db[12]);
        accb += g0+g1+g2+g3;
        float g01 = g0+g1, g12 = g1+g2, g23 = g2+g3;
        #pragma unroll
        for (int ky = 0; ky < 3; ++ky) {
            int yy = y + ky - 1; if ((unsigned)yy >= (unsigned)R) continue;
            if constexpr (UP) {
                const float* srow = in + (yy>>1)*H*4;
                int hx = x0 >> 1;
                float4 s0 = ldz4(srow + (hx-1)*4, hx > 0);
                float4 s1 = *reinterpret_cast<const float4*>(srow + hx*4);
                float4 s2 = *reinterpret_cast<const float4*>(srow + (hx+1)*4);
                float4 s3 = ldz4(srow + (hx+2)*4, hx+2 < H);
                accum4(&acc[ky*3+0], g0, s0); accum4(&acc[ky*3+0], g12, s1); accum4(&acc[ky*3+0], g3, s2);
                accum4(&acc[ky*3+1], g01, s1); accum4(&acc[ky*3+1], g23, s2);
                accum4(&acc[ky*3+2], g0, s1); accum4(&acc[ky*3+2], g12, s2); accum4(&acc[ky*3+2], g3, s3);
            } else {
                const float* row = in + yy*R*4;
                float4 p[6];
                #pragma unroll
                for (int k = 0; k < 6; ++k) {
                    int xx = x0 - 1 + k;
                    p[k] = ldz4(row + xx*4, (unsigned)xx < (unsigned)R);
                }
                float g[4] = {g0,g1,g2,g3};
                #pragma unroll
                for (int kx = 0; kx < 3; ++kx)
                    #pragma unroll
                    for (int j = 0; j < 4; ++j)
                        accum4(&acc[ky*3+kx], g[j], p[j+kx]);
            }
        }
    }
    unsigned lane = tid & 31;
    #pragma unroll
    for (int off = 16; off >= 4; off >>= 1) {
        #pragma unroll
        for (int i = 0; i < 36; ++i) acc[i] += __shfl_xor_sync(0xffffffffu, acc[i], off);
        accb += __shfl_xor_sync(0xffffffffu, accb, off);
    }
    if (lane < 4) {
        #pragma unroll
        for (int i = 0; i < 36; ++i) atomicAdd(&sRed[o*36 + i], acc[i]);
        atomicAdd(&sRed[144 + o], accb);
    }
}

template<int R>
__device__ __noinline__ void wgradfin_acc(const bf16* __restrict__ dout, const float* in,
                                          float* sRed, int tid, int nth)
{
    constexpr int NX = R/4;
    float acc[36]; float accb = 0.f;
    #pragma unroll
    for (int i = 0; i < 36; ++i) acc[i] = 0.f;
    for (int pv = tid; pv < R*NX; pv += nth) {
        int y = pv / NX, x0 = (pv % NX)*4;
        float4 g = ld4h(dout + y*R + x0);
        float gv[4] = {g.x,g.y,g.z,g.w};
        accb += g.x+g.y+g.z+g.w;
        #pragma unroll
        for (int ky = 0; ky < 3; ++ky) {
            int yy = y + ky - 1; if ((unsigned)yy >= (unsigned)R) continue;
            const float* row = in + yy*R*4;
            float4 p[6];
            #pragma unroll
            for (int k = 0; k < 6; ++k) {
                int xx = x0 - 1 + k;
                p[k] = ldz4(row + xx*4, (unsigned)xx < (unsigned)R);
            }
            #pragma unroll
            for (int kx = 0; kx < 3; ++kx)
                #pragma unroll
                for (int j = 0; j < 4; ++j)
                    accum4(&acc[ky*3+kx], gv[j], p[j+kx]);
        }
    }
    unsigned lane = tid & 31;
    #pragma unroll
    for (int off = 16; off >= 1; off >>= 1) {
        #pragma unroll
        for (int i = 0; i < 36; ++i) acc[i] += __shfl_xor_sync(0xffffffffu, acc[i], off);
        accb += __shfl_xor_sync(0xffffffffu, accb, off);
    }
    if (lane == 0) {
        #pragma unroll
        for (int i = 0; i < 36; ++i) atomicAdd(&sRed[i], acc[i]);
        atomicAdd(&sRed[36], accb);
    }
}

template<int R>
__device__ __noinline__ void wgradfirst_acc(const bf16* __restrict__ dout, const float* __restrict__ in,
                                            float* sRed, int tid, int nth)
{
    constexpr int NX = R/4;
    const int o = tid & 3;
    float acc[9]; float accb = 0.f;
    #pragma unroll
    for (int i = 0; i < 9; ++i) acc[i] = 0.f;
    for (int pv = tid >> 2; pv < R*NX; pv += nth >> 2) {
        int y = pv / NX, x0 = (pv % NX)*4;
        const bf16* db = dout + (y*R + x0)*4 + o;
        float g[4] = {bf2f(db[0]), bf2f(db[4]), bf2f(db[8]), bf2f(db[12])};
        accb += g[0]+g[1]+g[2]+g[3];
        #pragma unroll
        for (int ky = 0; ky < 3; ++ky) {
            int yy = y + ky - 1; if ((unsigned)yy >= (unsigned)R) continue;
            const float* row = in + yy*R;
            float4 v = *reinterpret_cast<const float4*>(row + x0);
            float s[6];
            s[0] = (x0 > 0)   ? row[x0-1] : 0.f;
            s[1]=v.x; s[2]=v.y; s[3]=v.z; s[4]=v.w;
            s[5] = (x0+4 < R) ? row[x0+4] : 0.f;
            #pragma unroll
            for (int kx = 0; kx < 3; ++kx) {
                float t = 0.f;
                #pragma unroll
                for (int j = 0; j < 4; ++j) t = fmaf(g[j], s[j+kx], t);
                acc[ky*3+kx] += t;
            }
        }
    }
    unsigned lane = tid & 31;
    #pragma unroll
    for (int off = 16; off >= 4; off >>= 1) {
        #pragma unroll
        for (int i = 0; i < 9; ++i) acc[i] += __shfl_xor_sync(0xffffffffu, acc[i], off);
        accb += __shfl_xor_sync(0xffffffffu, accb, off);
    }
    if (lane < 4) {
        #pragma unroll
        for (int i = 0; i < 9; ++i) atomicAdd(&sRed[o*9 + i], acc[i]);
        atomicAdd(&sRed[36 + o], accb);
    }
}

// deferred weight update: reads sRed, applies SGD step, re-zeroes sRed
__device__ __forceinline__ void apply_update(float* w, float* b, float* sRed, int nw, int nb)
{
    for (int i = threadIdx.x; i < nw; i += NT) { w[i] -= LRATE * sRed[i]; sRed[i] = 0.f; }
    for (int i = threadIdx.x; i < nb; i += NT) { b[i] -= LRATE * sRed[nw+i]; sRed[nw+i] = 0.f; }
}

// ---- full forward pass ----
template<bool FIRST>
__device__ __noinline__ void forward_pass(const float* __restrict__ x, const float* sP,
                                          float* sT, bf16* Sh, float* gQ4,
                                          unsigned char* I, float* __restrict__ ydst)
{
    conv0pool<128,FIRST>(x, sP+PW0, sP+PEB, Sh+HU0, sT+T_P0, I+IX0);               __syncthreads();
    conv4pool<64,FIRST>(sT+T_P0, sP+PEW,     sP+PEB+4,  Sh+HU1, sT+T_P1, I+IX1);   __syncthreads();
    conv4pool<32,FIRST>(sT+T_P1, sP+PEW+144, sP+PEB+8,  Sh+HU2, sT+T_P2, I+IX2);   __syncthreads();
    conv4pool<16,FIRST>(sT+T_P2, sP+PEW+288, sP+PEB+12, Sh+HU3, sT+T_P3, I+IX3);   __syncthreads();
    conv4pool<8,FIRST> (sT+T_P3, sP+PEW+432, sP+PEB+16, Sh+HU4, sT+T_P4, I+IX4);   __syncthreads();
    conv4b<4,FIRST>    (sT+T_P4, sP+PEW+576, sP+PEB+20, Sh+HU5, sT+T_F);           __syncthreads();

    if (threadIdx.x < 32) {
        float acc = sP[PLEB + threadIdx.x];
        for (int j = 0; j < 64; ++j) acc += sP[PLEW + threadIdx.x*64 + j] * sT[T_F + nh(j)];
        if (FIRST) Sh[HZU + threadIdx.x] = f2bf(acc);
        sT[T_Z + threadIdx.x] = swish_f(acc);
    }
    __syncthreads();
    if (threadIdx.x < 64) {
        float acc = sP[PLDB + threadIdx.x];
        for (int j = 0; j < 32; ++j) acc += sP[PLDW + threadIdx.x*32 + j] * sT[T_Z + j];
        int ni = nh(threadIdx.x);
        if (FIRST) Sh[HDU + ni] = f2bf(acc);
        sT[T_DD + ni] = swish_f(acc);
    }
    __syncthreads();

    convup<8,FIRST>  (sT+T_DD, sP+PDW,     sP+PDB,    Sh+HV0, sT+T_Q0);            __syncthreads();
    convup<16,FIRST> (sT+T_Q0, sP+PDW+144, sP+PDB+4,  Sh+HV1, sT+T_Q1);            __syncthreads();
    convup<32,FIRST> (sT+T_Q1, sP+PDW+288, sP+PDB+8,  Sh+HV2, sT+T_Q2);            __syncthreads();
    convup<64,FIRST> (sT+T_Q2, sP+PDW+432, sP+PDB+12, Sh+HV3, sT+T_Q3);            __syncthreads();
    convup<128,FIRST>(sT+T_Q3, sP+PDW+576, sP+PDB+16, Sh+HV4, gQ4);                __syncthreads();

    if (FIRST) convfin<128,2>(gQ4, sP+PWO, sP[PBO], Sh+HDY, x);
    else       convfin<128,0>(gQ4, sP+PWO, sP[PBO], ydst, nullptr);
    __syncthreads();
}

__global__ __launch_bounds__(NT, 1)
void maml_kernel(const float* __restrict__ x_all,
                 const float* __restrict__ enc_w0,   const float* __restrict__ enc_w,
                 const float* __restrict__ enc_b,    const float* __restrict__ enc_lin_w,
                 const float* __restrict__ enc_lin_b,const float* __restrict__ dec_lin_w,
                 const float* __restrict__ dec_lin_b,const float* __restrict__ dec_w,
                 const float* __restrict__ dec_b,    const float* __restrict__ dec_w_out,
                 const float* __restrict__ dec_b_out,float* __restrict__ out)
{
    extern __shared__ __align__(16) float smem_f[];
    float* sT    = smem_f;
    float* sP    = smem_f + T_END;
    float* sRedA = smem_f + T_END + NPARAM_PAD;
    float* sRedB = sRedA + 160;
    float* sWE   = sRedB + 160;

    const int s = blockIdx.x;
    bf16*  Sh  = g_scratchh + (size_t)s * SSCH;
    float* gQ4 = g_q4 + (size_t)s * 65536;
    unsigned char* I = g_idxbuf + s * SIDX;
    const float* x = x_all + (size_t)s * 16384;

    for (int i = threadIdx.x; i < 36;   i += NT) sP[PW0 +i] = enc_w0[i];
    for (int i = threadIdx.x; i < 24;   i += NT) sP[PEB +i] = enc_b[i];
    for (int i = threadIdx.x; i < 720;  i += NT) sP[PEW +i] = enc_w[i];
    for (int i = threadIdx.x; i < 2048; i += NT) sP[PLEW+i] = enc_lin_w[i];
    for (int i = threadIdx.x; i < 32;   i += NT) sP[PLEB+i] = enc_lin_b[i];
    for (int i = threadIdx.x; i < 2048; i += NT) sP[PLDW+i] = dec_lin_w[i];
    for (int i = threadIdx.x; i < 64;   i += NT) sP[PLDB+i] = dec_lin_b[i];
    for (int i = threadIdx.x; i < 720;  i += NT) sP[PDW +i] = dec_w[i];
    for (int i = threadIdx.x; i < 20;   i += NT) sP[PDB +i] = dec_b[i];
    for (int i = threadIdx.x; i < 36;   i += NT) sP[PWO +i] = dec_w_out[i];
    for (int i = threadIdx.x; i < 160;  i += NT) { sRedA[i] = 0.f; sRedB[i] = 0.f; }
    if (threadIdx.x == 0) sP[PBO] = dec_b_out[0];
    __syncthreads();

    // ===== forward #1 =====
    forward_pass<true>(x, sP, sT, Sh, gQ4, I, nullptr);

    // ===== precompute dupv effective-4x4 weight tables into smem =====
    for (int e = threadIdx.x; e < 1280; e += NT) {
        int l = e >> 8, r = e & 255;
        int c = r >> 6, di = r & 63;
        int o = di & 3, ij = di >> 2, i = ij >> 2, j = ij & 3;
        const float* wb = sP + PDW + l*144 + (o*4 + c)*9;
        float sacc = 0.f;
        #pragma unroll
        for (int sy = 0; sy < 2; ++sy) {
            int a = sy + 2 - i; if (a < 0 || a > 2) continue;
            #pragma unroll
            for (int sx = 0; sx < 2; ++sx) {
                int bc = sx + 2 - j; if (bc < 0 || bc > 2) continue;
                sacc += wb[a*3 + bc];
            }
        }
        sWE[l*260 + c*65 + di] = sacc;
    }
    __syncthreads();

    bf16* GA = Sh + HGA;
    bf16* GB = Sh + HGB;
    const int tid = threadIdx.x;

    // ===== backward: warp-split merged (dgrad || wgrad) phases =====
    if (tid < 256) dgrad_fin<128>(Sh+HDY, sP+PWO, Sh+HV4, GA, tid, 256);
    else           wgradfin_acc<128>(Sh+HDY, gQ4, sRedA, tid-256, 256);
    __syncthreads();
    apply_update(sP+PWO, sP+PBO, sRedA, 36, 1);

    if (tid < 256) dupv<128>(GA, sWE, 4, Sh+HV3, GB, tid, 256);
    else           wgrad4_acc<128,true>(GA, sT+T_Q3, sRedB, tid-256, 256);
    __syncthreads();
    apply_update(sP+PDW+576, sP+PDB+16, sRedB, 144, 4);

    if (tid < 256) dupv<64>(GB, sWE, 3, Sh+HV2, GA, tid, 256);
    else           wgrad4_acc<64,true>(GB, sT+T_Q2, sRedA, tid-256, 256);
    __syncthreads();
    apply_update(sP+PDW+432, sP+PDB+12, sRedA, 144, 4);

    if (tid < 256) dupv<32>(GA, sWE, 2, Sh+HV1, GB, tid, 256);
    else           wgrad4_acc<32,true>(GA, sT+T_Q1, sRedB, tid-256, 256);
    __syncthreads();
    apply_update(sP+PDW+288, sP+PDB+8, sRedB, 144, 4);

    if (tid < 256) dupv<16>(GB, sWE, 1, Sh+HV0, GA, tid, 256);
    else           wgrad4_acc<16,true>(GB, sT+T_Q0, sRedA, tid-256, 256);
    __syncthreads();
    apply_update(sP+PDW+144, sP+PDB+4, sRedA, 144, 4);

    if (tid < 256) dupv<8>(GA, sWE, 0, Sh+HDU, GB, tid, 256);    // GB = ddu (NHWC, 64)
    else           wgrad4_acc<8,true>(GA, sT+T_DD, sRedB, tid-256, 256);
    __syncthreads();
    apply_update(sP+PDW, sP+PDB, sRedB, 144, 4);

    // dec_lin / enc_lin backward
    if (tid < 32) {
        float acc = 0.f;
        for (int i = 0; i < 64; ++i) acc += sP[PLDW + i*32 + tid] * bf2f(GB[nh(i)]);
        GA[tid] = f2bf(acc);                 // dz
    }
    __syncthreads();
    for (int t = tid; t < 2048; t += NT) {
        int i = t >> 5, j = t & 31;
        sP[PLDW + t] -= LRATE * bf2f(GB[nh(i)]) * sT[T_Z + j];
    }
    if (tid < 64) sP[PLDB + tid] -= LRATE * bf2f(GB[nh(tid)]);
    __syncthreads();
    if (tid < 32)
        GB[tid] = f2bf(bf2f(GA[tid]) * swish_d(bf2f(Sh[HZU + tid]))); // dzu
    __syncthreads();
    if (tid < 64) {
        float acc = 0.f;
        for (int i = 0; i < 32; ++i) acc += sP[PLEW + i*64 + tid] * bf2f(GB[i]);
        int ni = nh(tid);
        GA[ni] = f2bf(acc * swish_d(bf2f(Sh[HU5 + ni])));   // du5 (NHWC)
    }
    __syncthreads();
    for (int t = tid; t < 2048; t += NT) {
        int i = t >> 6, j = t & 63;
        sP[PLEW + t] -= LRATE * bf2f(GB[i]) * sT[T_F + nh(j)];
    }
    if (tid < 32) sP[PLEB + tid] -= LRATE * bf2f(GB[tid]);
    __syncthreads();

    // encoder backward: fused dgrad+pool-scatter || wgrad, 5 levels
    if (tid < 256) dgrad4pb<4>(GA, sP+PEW+576, I+IX4, Sh+HU4, GB, tid, 256);
    else           wgrad4_acc<4,false>(GA, sT+T_P4, sRedA, tid-256, 256);
    __syncthreads();
    apply_update(sP+PEW+576, sP+PEB+20, sRedA, 144, 4);

    if (tid < 256) dgrad4pb<8>(GB, sP+PEW+432, I+IX3, Sh+HU3, GA, tid, 256);
    else           wgrad4_acc<8,false>(GB, sT+T_P3, sRedB, tid-256, 256);
    __syncthreads();
    apply_update(sP+PEW+432, sP+PEB+16, sRedB, 144, 4);

    if (tid < 256) dgrad4pb<16>(GA, sP+PEW+288, I+IX2, Sh+HU2, GB, tid, 256);
    else           wgrad4_acc<16,false>(GA, sT+T_P2, sRedA, tid-256, 256);
    __syncthreads();
    apply_update(sP+PEW+288, sP+PEB+12, sRedA, 144, 4);

    if (tid < 256) dgrad4pb<32>(GB, sP+PEW+144, I+IX1, Sh+HU1, GA, tid, 256);
    else           wgrad4_acc<32,false>(GB, sT+T_P1, sRedB, tid-256, 256);
    __syncthreads();
    apply_update(sP+PEW+144, sP+PEB+8, sRedB, 144, 4);

    if (tid < 256) dgrad4pb<64>(GA, sP+PEW, I+IX0, Sh+HU0, GB, tid, 256);
    else           wgrad4_acc<64,false>(GA, sT+T_P0, sRedA, tid-256, 256);
    __syncthreads();
    apply_update(sP+PEW, sP+PEB+4, sRedA, 144, 4);

    wgradfirst_acc<128>(GB, x, sRedB, tid, NT);
    __syncthreads();
    apply_update(sP+PW0, sP+PEB, sRedB, 36, 4);
    __syncthreads();   // W0 update must be visible to fwd2's conv0pool

    // ===== forward #2 with updated per-sample params =====
    forward_pass<false>(x, sP, sT, Sh, gQ4, I, out + (size_t)s * 16384);
}

extern "C" void kernel_launch(void* const* d_in, const int* in_sizes, int n_in,
                              void* d_out, int out_size)
{
    (void)in_sizes; (void)n_in; (void)out_size;
    cudaFuncSetAttribute(maml_kernel, cudaFuncAttributeMaxDynamicSharedMemorySize, SMEM_BYTES);
    maml_kernel<<<128, NT, SMEM_BYTES>>>(
        (const float*)d_in[0],  (const float*)d_in[1],  (const float*)d_in[2],
        (const float*)d_in[3],  (const float*)d_in[4],  (const float*)d_in[5],
        (const float*)d_in[6],  (const float*)d_in[7],  (const float*)d_in[8],
        (const float*)d_in[9],  (const float*)d_in[10], (const float*)d_in[11],
        (float*)d_out);
}